// round 6
// baseline (speedup 1.0000x reference)
#include <cuda_runtime.h>
#include <cstdint>

// Problem constants (fixed by the reference):
//   B=64 batches, R=32 rows, N=16384 context nodes, D=64 dim, O=8 types.
//
// Identity: avg_sim[b,r] = dot(norm_l[b,r], S[b]) / nvalid[b],
//   S[b] = sum over valid n of l2norm(h_context[b,n]).
// fmask density ~0.75% -> never read invalid h_context rows.
//
// R3: shared float2 LDS at 4-mod-8 offset trapped -> s_acc now first+aligned,
//     and the epilogue uses scalar shared reads (no >4B shared alignment
//     requirement anywhere).
// R4/R5: broker container failures (no kernel signal); resubmitting the fused
//     design with the scalar-LDS hedge.

#define BB 64
#define RR 32
#define NCTX 16384
#define DD 64
#define OO 8

#define NT 512                       // threads per block (16 warps)
#define CHUNK 4096
#define NCHUNKS (NCTX / CHUNK)       // 4

__global__ __launch_bounds__(NT) void fused_kernel(
    const float* __restrict__ l_local,   // [B, R, D]
    const float* __restrict__ hctx,      // [B, N, D]
    const float* __restrict__ lambda_so, // [R, O]
    const int*  __restrict__ center_o,   // [B]
    const int*  __restrict__ o_types,    // [B, N]
    const int*  __restrict__ adj,        // [B, N] bool widened to int32
    const int*  __restrict__ two_hop,    // [B, N] bool widened to int32
    float* __restrict__ out)             // [B, R]
{
    const int b    = blockIdx.x;
    const int tid  = threadIdx.x;
    const int wid  = tid >> 5;
    const int lane = tid & 31;
    const int ctr  = center_o[b];

    __shared__ __align__(16) float s_acc[DD];
    __shared__ int   s_cnt;
    __shared__ int   s_idx[CHUNK];

    if (tid < DD) s_acc[tid] = 0.0f;

    const int4* ot4 = reinterpret_cast<const int4*>(o_types) + ((long)b * NCTX >> 2);
    const int4* aj4 = reinterpret_cast<const int4*>(adj)     + ((long)b * NCTX >> 2);
    const int4* th4 = reinterpret_cast<const int4*>(two_hop) + ((long)b * NCTX >> 2);
    const float* hb = hctx + (size_t)b * NCTX * DD;

    float a0 = 0.0f, a1 = 0.0f;   // per-thread partial of S[b] at cols 2*lane(+1)
    int   total_cnt = 0;

    for (int c = 0; c < NCHUNKS; ++c) {
        const int n0 = c * CHUNK;
        if (tid == 0) s_cnt = 0;
        __syncthreads();

        // --- Phase 1: vectorized mask scan (CHUNK/4 = 1024 int4 / 512 thr = 2 iters)
        #pragma unroll
        for (int it = 0; it < CHUNK / 4 / NT; ++it) {
            int q = (n0 >> 2) + it * NT + tid;       // int4 index within batch
            int4 t = ot4[q];
            int4 a = aj4[q];
            int4 h = th4[q];
            int m0 = (t.x == ctr) & ((a.x | h.x) != 0);
            int m1 = (t.y == ctr) & ((a.y | h.y) != 0);
            int m2 = (t.z == ctr) & ((a.z | h.z) != 0);
            int m3 = (t.w == ctr) & ((a.w | h.w) != 0);
            int cc = m0 + m1 + m2 + m3;
            if (cc) {
                int p = atomicAdd(&s_cnt, cc);
                int nb = q * 4;                      // absolute n
                if (m0) s_idx[p++] = nb + 0;
                if (m1) s_idx[p++] = nb + 1;
                if (m2) s_idx[p++] = nb + 2;
                if (m3) s_idx[p]   = nb + 3;
            }
        }
        __syncthreads();
        const int cnt = s_cnt;
        total_cnt += cnt;

        // --- Phase 2: warp-per-row gather + l2-normalize + accumulate (regs)
        // Global rows are 256B-aligned: (b*NCTX+idx)*64 floats.
        for (int i = wid; i < cnt; i += NT / 32) {
            const float2* row = reinterpret_cast<const float2*>(
                hb + (size_t)s_idx[i] * DD);
            float2 v = row[lane];                    // cols 2*lane, 2*lane+1
            float sq = v.x * v.x + v.y * v.y;
            #pragma unroll
            for (int o = 16; o; o >>= 1) sq += __shfl_xor_sync(0xffffffffu, sq, o);
            float rs = rsqrtf(fmaxf(sq, 1e-12f));    // tf.nn.l2_normalize eps
            a0 += v.x * rs;
            a1 += v.y * rs;
        }
        __syncthreads();   // s_idx reuse barrier (gather reads done before next scan)
    }

    // --- Merge per-thread partials into s_acc (16 warps -> 16-deep atomics max)
    atomicAdd(&s_acc[lane * 2 + 0], a0);
    atomicAdd(&s_acc[lane * 2 + 1], a1);
    __syncthreads();

    // --- Epilogue: warp per r (16 warps, 32 r's -> 2 each).
    // Scalar shared reads only (no LDS.64 on shared).
    const float nv  = (float)total_cnt;
    const float Sx  = s_acc[lane * 2 + 0];
    const float Sy  = s_acc[lane * 2 + 1];
    const float inv_nv_sim = 1.0f / fmaxf(nv, 1e-9f);
    const float inv_nv_lam = 1.0f / fmaxf(nv, 1.0f);

    for (int r = wid; r < RR; r += NT / 32) {
        const float2* row = reinterpret_cast<const float2*>(
            l_local + ((size_t)b * RR + r) * DD);   // 256B-aligned rows
        float2 v = row[lane];
        float sq = v.x * v.x + v.y * v.y;
        float dp = v.x * Sx + v.y * Sy;
        #pragma unroll
        for (int o = 16; o; o >>= 1) {
            sq += __shfl_xor_sync(0xffffffffu, sq, o);
            dp += __shfl_xor_sync(0xffffffffu, dp, o);
        }
        float rs  = rsqrtf(fmaxf(sq, 1e-12f));
        float avg = dp * rs * inv_nv_sim;
        float lam = lambda_so[r * OO + ctr];
        float w   = fmaxf(lam * inv_nv_lam, 0.0f) * (1.0f - avg);
        if (lane == 0) out[(size_t)b * RR + r] = w;
    }
}

// ---------------------------------------------------------------------------
// Inputs per metadata order:
//   0: l_local f32 [B,R,D]   1: h_context f32 [B,N,D]   2: lambda_so f32 [R,O]
//   3: center_o i32 [B]      4: o_types i32 [B,N]
//   5: adj_mask bool->i32 [B,N]   6: two_hop_mask bool->i32 [B,N]
// Output: f32 [B,R]
// ---------------------------------------------------------------------------
extern "C" void kernel_launch(void* const* d_in, const int* in_sizes, int n_in,
                              void* d_out, int out_size) {
    fused_kernel<<<BB, NT>>>(
        (const float*)d_in[0], (const float*)d_in[1], (const float*)d_in[2],
        (const int*)d_in[3], (const int*)d_in[4],
        (const int*)d_in[5], (const int*)d_in[6],
        (float*)d_out);
}

// round 7
// speedup vs baseline: 1.1860x; 1.1860x over previous
#include <cuda_runtime.h>
#include <cstdint>

// Problem constants (fixed by the reference):
//   B=64 batches, R=32 rows, N=16384 context nodes, D=64 dim, O=8 types.
//
// Identity: avg_sim[b,r] = dot(norm_l[b,r], S[b]) / nvalid[b],
//   S[b] = sum over valid n of l2norm(h_context[b,n]).
// fmask density ~0.75% -> never read invalid h_context rows.
//
// R6 finding: kernel was LATENCY-bound (DRAM 9.5%, issue 12%): the 4-chunk
// loop serialized 4x {scan -> bar -> gather -> bar}, each >= 2 DRAM round
// trips. Fix: scan ALL 16384 nodes in one fully-unrolled pass (24 independent
// loads/thread, deep MLP) into a 32KB smem index list, ONE barrier, one
// gather, epilogue. Critical path ~3k cycles instead of ~12k.

#define BB 64
#define RR 32
#define NCTX 16384
#define DD 64
#define OO 8

#define NT 512                       // threads per block (16 warps)
#define IDX_CAP 8192                 // 32KB; expected valid ~122 (67x margin)

__global__ __launch_bounds__(NT) void fused_kernel(
    const float* __restrict__ l_local,   // [B, R, D]
    const float* __restrict__ hctx,      // [B, N, D]
    const float* __restrict__ lambda_so, // [R, O]
    const int*  __restrict__ center_o,   // [B]
    const int*  __restrict__ o_types,    // [B, N]
    const int*  __restrict__ adj,        // [B, N] bool widened to int32
    const int*  __restrict__ two_hop,    // [B, N] bool widened to int32
    float* __restrict__ out)             // [B, R]
{
    const int b    = blockIdx.x;
    const int tid  = threadIdx.x;
    const int wid  = tid >> 5;
    const int lane = tid & 31;
    const int ctr  = center_o[b];

    __shared__ __align__(16) float s_acc[DD];
    __shared__ int   s_cnt;
    __shared__ int   s_idx[IDX_CAP];

    if (tid < DD) s_acc[tid] = 0.0f;
    if (tid == 0) s_cnt = 0;
    __syncthreads();

    const int4* ot4 = reinterpret_cast<const int4*>(o_types) + ((long)b * NCTX >> 2);
    const int4* aj4 = reinterpret_cast<const int4*>(adj)     + ((long)b * NCTX >> 2);
    const int4* th4 = reinterpret_cast<const int4*>(two_hop) + ((long)b * NCTX >> 2);
    const float* hb = hctx + (size_t)b * NCTX * DD;

    // --- Phase 1: single full scan. NCTX/4 = 4096 int4 / 512 thr = 8 iters,
    // fully unrolled: all 24 loads/thread independent -> deep MLP, one
    // DRAM-latency drain instead of 4 serialized rounds.
    #pragma unroll
    for (int it = 0; it < NCTX / 4 / NT; ++it) {
        int q = it * NT + tid;                   // int4 index within batch
        int4 t = ot4[q];
        int4 a = aj4[q];
        int4 h = th4[q];
        int m0 = (t.x == ctr) & ((a.x | h.x) != 0);
        int m1 = (t.y == ctr) & ((a.y | h.y) != 0);
        int m2 = (t.z == ctr) & ((a.z | h.z) != 0);
        int m3 = (t.w == ctr) & ((a.w | h.w) != 0);
        int cc = m0 + m1 + m2 + m3;
        if (cc) {
            int p = atomicAdd(&s_cnt, cc);
            if (p + cc <= IDX_CAP) {             // overflow clamp (never at 0.75%)
                int nb = q * 4;                  // absolute n
                if (m0) s_idx[p++] = nb + 0;
                if (m1) s_idx[p++] = nb + 1;
                if (m2) s_idx[p++] = nb + 2;
                if (m3) s_idx[p]   = nb + 3;
            }
        }
    }
    __syncthreads();
    const int cnt  = s_cnt;
    const int gcnt = cnt < IDX_CAP ? cnt : IDX_CAP;

    // --- Phase 2: warp-per-row gather + l2-normalize + accumulate (regs).
    // Rows are 256B-aligned: (b*NCTX+idx)*64 floats.
    float a0 = 0.0f, a1 = 0.0f;                  // partial S[b] at cols 2*lane(+1)
    for (int i = wid; i < gcnt; i += NT / 32) {
        const float2* row = reinterpret_cast<const float2*>(
            hb + (size_t)s_idx[i] * DD);
        float2 v = row[lane];                    // cols 2*lane, 2*lane+1
        float sq = v.x * v.x + v.y * v.y;
        #pragma unroll
        for (int o = 16; o; o >>= 1) sq += __shfl_xor_sync(0xffffffffu, sq, o);
        float rs = rsqrtf(fmaxf(sq, 1e-12f));    // tf.nn.l2_normalize eps
        a0 += v.x * rs;
        a1 += v.y * rs;
    }

    // --- Merge per-thread partials into s_acc (16-deep atomic max per addr)
    atomicAdd(&s_acc[lane * 2 + 0], a0);
    atomicAdd(&s_acc[lane * 2 + 1], a1);
    __syncthreads();

    // --- Epilogue: warp per r (16 warps, 32 r's -> 2 each). Scalar LDS only.
    const float nv  = (float)cnt;
    const float Sx  = s_acc[lane * 2 + 0];
    const float Sy  = s_acc[lane * 2 + 1];
    const float inv_nv_sim = 1.0f / fmaxf(nv, 1e-9f);
    const float inv_nv_lam = 1.0f / fmaxf(nv, 1.0f);

    for (int r = wid; r < RR; r += NT / 32) {
        const float2* row = reinterpret_cast<const float2*>(
            l_local + ((size_t)b * RR + r) * DD);   // 256B-aligned rows
        float2 v = row[lane];
        float sq = v.x * v.x + v.y * v.y;
        float dp = v.x * Sx + v.y * Sy;
        #pragma unroll
        for (int o = 16; o; o >>= 1) {
            sq += __shfl_xor_sync(0xffffffffu, sq, o);
            dp += __shfl_xor_sync(0xffffffffu, dp, o);
        }
        float rs  = rsqrtf(fmaxf(sq, 1e-12f));
        float avg = dp * rs * inv_nv_sim;
        float lam = lambda_so[r * OO + ctr];
        float w   = fmaxf(lam * inv_nv_lam, 0.0f) * (1.0f - avg);
        if (lane == 0) out[(size_t)b * RR + r] = w;
    }
}

// ---------------------------------------------------------------------------
// Inputs per metadata order:
//   0: l_local f32 [B,R,D]   1: h_context f32 [B,N,D]   2: lambda_so f32 [R,O]
//   3: center_o i32 [B]      4: o_types i32 [B,N]
//   5: adj_mask bool->i32 [B,N]   6: two_hop_mask bool->i32 [B,N]
// Output: f32 [B,R]
// ---------------------------------------------------------------------------
extern "C" void kernel_launch(void* const* d_in, const int* in_sizes, int n_in,
                              void* d_out, int out_size) {
    fused_kernel<<<BB, NT>>>(
        (const float*)d_in[0], (const float*)d_in[1], (const float*)d_in[2],
        (const int*)d_in[3], (const int*)d_in[4],
        (const int*)d_in[5], (const int*)d_in[6],
        (float*)d_out);
}

// round 11
// speedup vs baseline: 1.5055x; 1.2694x over previous
#include <cuda_runtime.h>
#include <cstdint>

// Problem constants (fixed by the reference):
//   B=64 batches, R=32 rows, N=16384 context nodes, D=64 dim, O=8 types.
//
// Identity: avg_sim[b,r] = dot(norm_l[b,r], S[b]) / nvalid[b],
//   S[b] = sum over valid n of l2norm(h_context[b,n]).
// fmask density ~0.75% -> never read invalid h_context rows.
//
// R7 finding: regs=32 killed scan MLP (24 int4 loads need 96 landing regs ->
// loads issued in batches of ~3, ~8 serialized memory round trips). And the
// gather ran ~8 dependent 5-deep SHFL chains per warp (~130cyc each, serial).
// R8: __launch_bounds__(512,1) -> 128-reg budget; load-all-then-process scan
// (MLP=24); gather pipelined 4 rows at a time.

#define BB 64
#define RR 32
#define NCTX 16384
#define DD 64
#define OO 8

#define NT 512                       // threads per block (16 warps)
#define NW (NT / 32)                 // 16 warps
#define SCAN_IT (NCTX / 4 / NT)      // 8 int4 per array per thread
#define IDX_CAP 8192                 // 32KB; expected valid ~122 (67x margin)

__global__ __launch_bounds__(NT, 1) void fused_kernel(
    const float* __restrict__ l_local,   // [B, R, D]
    const float* __restrict__ hctx,      // [B, N, D]
    const float* __restrict__ lambda_so, // [R, O]
    const int*  __restrict__ center_o,   // [B]
    const int*  __restrict__ o_types,    // [B, N]
    const int*  __restrict__ adj,        // [B, N] bool widened to int32
    const int*  __restrict__ two_hop,    // [B, N] bool widened to int32
    float* __restrict__ out)             // [B, R]
{
    const int b    = blockIdx.x;
    const int tid  = threadIdx.x;
    const int wid  = tid >> 5;
    const int lane = tid & 31;

    __shared__ __align__(16) float s_acc[DD];
    __shared__ int   s_cnt;
    __shared__ int   s_idx[IDX_CAP];

    if (tid < DD) s_acc[tid] = 0.0f;
    if (tid == 0) s_cnt = 0;
    __syncthreads();

    const int4* ot4 = reinterpret_cast<const int4*>(o_types) + ((long)b * NCTX >> 2);
    const int4* aj4 = reinterpret_cast<const int4*>(adj)     + ((long)b * NCTX >> 2);
    const int4* th4 = reinterpret_cast<const int4*>(two_hop) + ((long)b * NCTX >> 2);
    const float* hb = hctx + (size_t)b * NCTX * DD;

    // --- Phase 1: scan with forced MLP=24. Issue ALL loads first (landing
    // registers: 24 x int4 = 96 regs, within the 128-reg budget), then process.
    int4 vt[SCAN_IT], va[SCAN_IT], vh[SCAN_IT];
    #pragma unroll
    for (int it = 0; it < SCAN_IT; ++it) vt[it] = ot4[it * NT + tid];
    #pragma unroll
    for (int it = 0; it < SCAN_IT; ++it) va[it] = aj4[it * NT + tid];
    #pragma unroll
    for (int it = 0; it < SCAN_IT; ++it) vh[it] = th4[it * NT + tid];

    const int ctr = center_o[b];     // scalar load overlaps with the 24 above

    #pragma unroll
    for (int it = 0; it < SCAN_IT; ++it) {
        int4 t = vt[it], a = va[it], h = vh[it];
        int m0 = (t.x == ctr) & ((a.x | h.x) != 0);
        int m1 = (t.y == ctr) & ((a.y | h.y) != 0);
        int m2 = (t.z == ctr) & ((a.z | h.z) != 0);
        int m3 = (t.w == ctr) & ((a.w | h.w) != 0);
        int cc = m0 + m1 + m2 + m3;
        if (cc) {
            int p = atomicAdd(&s_cnt, cc);
            if (p + cc <= IDX_CAP) {             // overflow clamp (never at 0.75%)
                int nb = (it * NT + tid) * 4;    // absolute n
                if (m0) s_idx[p++] = nb + 0;
                if (m1) s_idx[p++] = nb + 1;
                if (m2) s_idx[p++] = nb + 2;
                if (m3) s_idx[p]   = nb + 3;
            }
        }
    }
    __syncthreads();
    const int cnt  = s_cnt;
    const int gcnt = cnt < IDX_CAP ? cnt : IDX_CAP;

    // --- Phase 2: warp-per-row gather, pipelined 4 rows per pass so the four
    // 5-deep SHFL reduction chains interleave instead of serializing.
    float a0 = 0.0f, a1 = 0.0f;                  // partial S[b] at cols 2*lane(+1)
    int i = wid;
    for (; i + 3 * NW < gcnt; i += 4 * NW) {
        const float2* r0 = reinterpret_cast<const float2*>(hb + (size_t)s_idx[i + 0 * NW] * DD);
        const float2* r1 = reinterpret_cast<const float2*>(hb + (size_t)s_idx[i + 1 * NW] * DD);
        const float2* r2 = reinterpret_cast<const float2*>(hb + (size_t)s_idx[i + 2 * NW] * DD);
        const float2* r3 = reinterpret_cast<const float2*>(hb + (size_t)s_idx[i + 3 * NW] * DD);
        float2 v0 = r0[lane], v1 = r1[lane], v2 = r2[lane], v3 = r3[lane];
        float s0 = v0.x * v0.x + v0.y * v0.y;
        float s1 = v1.x * v1.x + v1.y * v1.y;
        float s2 = v2.x * v2.x + v2.y * v2.y;
        float s3 = v3.x * v3.x + v3.y * v3.y;
        #pragma unroll
        for (int o = 16; o; o >>= 1) {
            s0 += __shfl_xor_sync(0xffffffffu, s0, o);
            s1 += __shfl_xor_sync(0xffffffffu, s1, o);
            s2 += __shfl_xor_sync(0xffffffffu, s2, o);
            s3 += __shfl_xor_sync(0xffffffffu, s3, o);
        }
        float q0 = rsqrtf(fmaxf(s0, 1e-12f));
        float q1 = rsqrtf(fmaxf(s1, 1e-12f));
        float q2 = rsqrtf(fmaxf(s2, 1e-12f));
        float q3 = rsqrtf(fmaxf(s3, 1e-12f));
        a0 += v0.x * q0 + v1.x * q1 + v2.x * q2 + v3.x * q3;
        a1 += v0.y * q0 + v1.y * q1 + v2.y * q2 + v3.y * q3;
    }
    for (; i < gcnt; i += NW) {                  // tail (<= 3 rows/warp)
        const float2* row = reinterpret_cast<const float2*>(hb + (size_t)s_idx[i] * DD);
        float2 v = row[lane];
        float sq = v.x * v.x + v.y * v.y;
        #pragma unroll
        for (int o = 16; o; o >>= 1) sq += __shfl_xor_sync(0xffffffffu, sq, o);
        float rs = rsqrtf(fmaxf(sq, 1e-12f));    // tf.nn.l2_normalize eps
        a0 += v.x * rs;
        a1 += v.y * rs;
    }

    // --- Merge per-thread partials into s_acc (16-deep atomic max per addr)
    atomicAdd(&s_acc[lane * 2 + 0], a0);
    atomicAdd(&s_acc[lane * 2 + 1], a1);
    __syncthreads();

    // --- Epilogue: warp per r (16 warps, 32 r's -> 2 each). Scalar LDS only.
    const float nv  = (float)cnt;
    const float Sx  = s_acc[lane * 2 + 0];
    const float Sy  = s_acc[lane * 2 + 1];
    const float inv_nv_sim = 1.0f / fmaxf(nv, 1e-9f);
    const float inv_nv_lam = 1.0f / fmaxf(nv, 1.0f);

    #pragma unroll
    for (int rr = 0; rr < RR / NW; ++rr) {
        int r = wid + rr * NW;
        const float2* row = reinterpret_cast<const float2*>(
            l_local + ((size_t)b * RR + r) * DD);   // 256B-aligned rows
        float2 v = row[lane];
        float sq = v.x * v.x + v.y * v.y;
        float dp = v.x * Sx + v.y * Sy;
        #pragma unroll
        for (int o = 16; o; o >>= 1) {
            sq += __shfl_xor_sync(0xffffffffu, sq, o);
            dp += __shfl_xor_sync(0xffffffffu, dp, o);
        }
        float rs  = rsqrtf(fmaxf(sq, 1e-12f));
        float avg = dp * rs * inv_nv_sim;
        float lam = lambda_so[r * OO + ctr];
        float w   = fmaxf(lam * inv_nv_lam, 0.0f) * (1.0f - avg);
        if (lane == 0) out[(size_t)b * RR + r] = w;
    }
}

// ---------------------------------------------------------------------------
// Inputs per metadata order:
//   0: l_local f32 [B,R,D]   1: h_context f32 [B,N,D]   2: lambda_so f32 [R,O]
//   3: center_o i32 [B]      4: o_types i32 [B,N]
//   5: adj_mask bool->i32 [B,N]   6: two_hop_mask bool->i32 [B,N]
// Output: f32 [B,R]
// ---------------------------------------------------------------------------
extern "C" void kernel_launch(void* const* d_in, const int* in_sizes, int n_in,
                              void* d_out, int out_size) {
    fused_kernel<<<BB, NT>>>(
        (const float*)d_in[0], (const float*)d_in[1], (const float*)d_in[2],
        (const int*)d_in[3], (const int*)d_in[4],
        (const int*)d_in[5], (const int*)d_in[6],
        (float*)d_out);
}